// round 1
// baseline (speedup 1.0000x reference)
#include <cuda_runtime.h>
#include <cstdint>

// Problem constants (fixed by the dataset: N=2048, DIM=16, E=65536)
#define NN 2048
#define DD 16

// scratch: per-node partial dot products (no cudaMalloc allowed)
__device__ float g_a[NN];  // dot(e[i], W[0:16])
__device__ float g_c[NN];  // dot(e[i], W[16:32])

// ---------------------------------------------------------------------------
// Kernel 1: per-node dot products with the two halves of W
// ---------------------------------------------------------------------------
__global__ void precompute_dots(const float* __restrict__ e,
                                const float* __restrict__ W, int n) {
    int i = blockIdx.x * blockDim.x + threadIdx.x;
    if (i >= n) return;
    float a = 0.f, c = 0.f;
#pragma unroll
    for (int k = 0; k < DD; k++) {
        float v = __ldg(&e[i * DD + k]);
        a += v * __ldg(&W[k]);
        c += v * __ldg(&W[DD + k]);
    }
    g_a[i] = a;
    g_c[i] = c;
}

// ---------------------------------------------------------------------------
// Kernel 2: zero the true_edges region (float4 vectorized)
// ---------------------------------------------------------------------------
__global__ void zero_te(float4* __restrict__ te4, size_t n4) {
    size_t t = (size_t)blockIdx.x * blockDim.x + threadIdx.x;
    if (t < n4) te4[t] = make_float4(0.f, 0.f, 0.f, 0.f);
}

// ---------------------------------------------------------------------------
// Kernel 3: scatter 1.0 at true-edge positions
// edge_list layout: [2, E] row-major -> src = el[t], dst = el[E + t]
// ---------------------------------------------------------------------------
__global__ void scatter_edges(const int* __restrict__ el,
                              float* __restrict__ te, int E, int n) {
    int t = blockIdx.x * blockDim.x + threadIdx.x;
    if (t >= E) return;
    int i = el[t];
    int j = el[E + t];
    te[(size_t)i * n + j] = 1.0f;
}

// ---------------------------------------------------------------------------
// Kernel 4 (the big one): write edge_embeddings + logits.
// 8 threads per pair p = i*N + j. Thread k in [0,8):
//   k<4  -> writes float4 #k of e[i]   to emb_out[p*8 + k]
//   k>=4 -> writes float4 #(k-4) of e[j] to emb_out[p*8 + k]
// Lane k==0 additionally writes logit[p] = (i!=j) ? a[i]+c[j]+b : -10.
// Warp = 4 consecutive pairs -> 512B fully contiguous stores.
// ---------------------------------------------------------------------------
__global__ void __launch_bounds__(256)
write_pairs(const float4* __restrict__ e4,   // [N*4] float4 (row = 4 float4)
            float4* __restrict__ emb_out,    // [N*N*8] float4
            float* __restrict__ logit_out,   // [N*N]
            const float* __restrict__ bptr) {
    size_t t = (size_t)blockIdx.x * blockDim.x + threadIdx.x;
    unsigned pair = (unsigned)(t >> 3);
    unsigned k = (unsigned)(t & 7u);
    unsigned i = pair >> 11;          // pair / 2048
    unsigned j = pair & 2047u;        // pair % 2048

    unsigned src = (k < 4u) ? (i * 4u + k) : (j * 4u + (k - 4u));
    float4 v = __ldg(&e4[src]);
    emb_out[(size_t)pair * 8 + k] = v;

    if (k == 0u) {
        float lg = (i != j) ? (g_a[i] + g_c[j] + __ldg(bptr)) : -10.0f;
        logit_out[pair] = lg;
    }
}

// ---------------------------------------------------------------------------
extern "C" void kernel_launch(void* const* d_in, const int* in_sizes, int n_in,
                              void* d_out, int out_size) {
    const float* emb   = (const float*)d_in[0];   // [N, 16]
    const int*   edges = (const int*)d_in[1];     // [2, E]
    const float* W     = (const float*)d_in[2];   // [1, 32]
    const float* b     = (const float*)d_in[3];   // [1]

    const int two_d = in_sizes[2];        // 32
    const int d     = two_d / 2;          // 16
    const int n     = in_sizes[0] / d;    // 2048
    const int E     = in_sizes[1] / 2;    // 65536

    float* out       = (float*)d_out;
    float* emb_out   = out;                                   // n*n*2d floats
    float* logit_out = out + (size_t)n * n * two_d;           // n*n floats
    float* te_out    = logit_out + (size_t)n * n;             // n*n floats

    // 1) per-node dots
    precompute_dots<<<(n + 255) / 256, 256>>>(emb, W, n);

    // 2) zero true_edges
    size_t te4 = ((size_t)n * n) / 4;
    zero_te<<<(unsigned)((te4 + 255) / 256), 256>>>((float4*)te_out, te4);

    // 3) scatter true edges
    scatter_edges<<<(E + 255) / 256, 256>>>(edges, te_out, E, n);

    // 4) main write: 8 threads per pair
    size_t threads = (size_t)n * n * 8;                       // 33,554,432
    unsigned blocks = (unsigned)(threads / 256);              // 131,072
    write_pairs<<<blocks, 256>>>((const float4*)emb, (float4*)emb_out,
                                 logit_out, b);
}